// round 6
// baseline (speedup 1.0000x reference)
#include <cuda_runtime.h>
#include <cstdint>

typedef unsigned long long ull;

#define CH    16
#define CATN  32
#define HID   128
#define KOUT  15
#define BB    8
#define HH    256
#define WW    256
#define NSTEP 10
#define NPIX  (BB*HH*WW)   // 524288

// ---------------- scratch (static __device__ — no allocs) ----------------
__device__ float g_d[NPIX*CH];          // conv output, NHWC, 32MB
__device__ float g_S[CATN*CATN];        // Gram matrix sums
__device__ float g_csum[CATN];          // per-channel sums of cat
__device__ ull   g_fc0p[HID*CATN];      // per-step scale-folded fc0 weights, packed (w,w)
__device__ ull   g_fc1p[HID*16];        // fc1 [o][k] packed (w,w); k=15 slot = BN shift
__device__ ull   g_convp[49*8];         // conv weights [tap][ch-pair]
__device__ ull   g_convbp[8];           // conv bias packed pairs
__device__ float g_fc0b[HID];
__device__ float g_gamma[HID];
__device__ float g_beta[HID];
__device__ int   g_mask_mode;           // 0=float32, 1=int32, 2=byte

// ---------------- f32x2 helpers ----------------
__device__ __forceinline__ ull fma2(ull a, ull b, ull c){
    ull d; asm("fma.rn.f32x2 %0,%1,%2,%3;" : "=l"(d) : "l"(a), "l"(b), "l"(c)); return d;
}
__device__ __forceinline__ ull add2(ull a, ull b){
    ull d; asm("add.rn.f32x2 %0,%1,%2;" : "=l"(d) : "l"(a), "l"(b)); return d;
}
__device__ __forceinline__ ull pack2(float lo, float hi){
    ull r; asm("mov.b64 %0,{%1,%2};" : "=l"(r) : "f"(lo), "f"(hi)); return r;
}
__device__ __forceinline__ void unpack2(ull v, float& lo, float& hi){
    asm("mov.b64 {%0,%1},%2;" : "=f"(lo), "=f"(hi) : "l"(v));
}

// reflect padding index (np.pad mode='reflect'), pad=3 < 256 so single reflection
__device__ __forceinline__ int refl(int t){
    if (t < 0)    t = -t;
    if (t >= 256) t = 510 - t;
    return t;
}

// ---------------- init: copy x->state, pack weights, classify 128-buffers, detect mask dtype ----
__global__ void init_kernel(const float* __restrict__ x,
                            const float* __restrict__ conv_w,
                            const float* __restrict__ conv_b,
                            const float* __restrict__ fc1_w,
                            const float* __restrict__ masks_raw,
                            const float* __restrict__ c0,
                            const float* __restrict__ c1,
                            const float* __restrict__ c2,
                            float* __restrict__ out)
{
    int idx = blockIdx.x*blockDim.x + threadIdx.x;
    int stride = gridDim.x*blockDim.x;
    const float4* xin = (const float4*)x;
    float4* xo = (float4*)out;
    for (int i = idx; i < NPIX*CH/4; i += stride) xo[i] = xin[i];

    if (blockIdx.x == 0){
        __shared__ int sel[3];   // indices of (fc0_b, gamma, beta) among {c0,c1,c2}
        if (threadIdx.x == 0){
            const float* cands[3] = {c0, c1, c2};
            int gi = -1, bi = -1;
            for (int c = 0; c < 3; c++){
                int ones = 0, zeros = 0;
                for (int i = 0; i < 128; i++){
                    float v = cands[c][i];
                    if (v == 1.0f) ones++;
                    if (v == 0.0f) zeros++;
                }
                if (ones == 128 && gi < 0) gi = c;
                else if (zeros == 128 && bi < 0) bi = c;
            }
            int fi;
            if (gi >= 0 && bi >= 0 && gi != bi) fi = 3 - gi - bi;
            else { fi = 0; gi = 1; bi = 2; }   // fallback: dict order fc0_b, gamma, beta
            sel[0] = fi; sel[1] = gi; sel[2] = bi;

            // mask dtype detection: Bernoulli(0.5) data makes these unambiguous.
            int mode = 2;
            bool okf = true;
            for (int i = 0; i < 1024; i++){
                float v = masks_raw[i];
                if (v != 0.f && v != 1.f){ okf = false; break; }
            }
            if (okf) mode = 0;
            else {
                const int* mm = (const int*)masks_raw;
                bool oki = true;
                for (int i = 0; i < 1024; i++){
                    int v = mm[i];
                    if (v != 0 && v != 1){ oki = false; break; }
                }
                mode = oki ? 1 : 2;
            }
            g_mask_mode = mode;
        }
        __syncthreads();
        {
            const float* cands[3] = {c0, c1, c2};
            if (threadIdx.x < 128){
                int t = threadIdx.x;
                g_fc0b[t]  = cands[sel[0]][t];
                g_gamma[t] = cands[sel[1]][t];
                g_beta[t]  = cands[sel[2]][t];
            }
        }
        // conv weights: conv_w[c*49 + tap]; pack channel pairs (2j,2j+1) per tap
        for (int i = threadIdx.x; i < 49*8; i += blockDim.x){
            int t = i >> 3, j = i & 7;
            g_convp[i] = pack2(conv_w[(2*j)*49 + t], conv_w[(2*j+1)*49 + t]);
        }
        if (threadIdx.x < 8)
            g_convbp[threadIdx.x] = pack2(conv_b[2*threadIdx.x], conv_b[2*threadIdx.x+1]);
        // fc1: fc1_w[k*HID + o] -> [o][k] packed; slot 15 = per-step shift (stats writes it)
        for (int i = threadIdx.x; i < HID*16; i += blockDim.x){
            int o = i >> 4, k = i & 15;
            float w = (k < KOUT) ? fc1_w[k*HID + o] : 0.f;
            g_fc1p[i] = pack2(w, w);
        }
        for (int i = threadIdx.x; i < CATN*CATN; i += blockDim.x) g_S[i] = 0.f;
        if (threadIdx.x < CATN) g_csum[threadIdx.x] = 0.f;
    }
}

// ---------------- pass 1: depthwise 7x7 reflect conv (f32x2) + cat moment accumulation -------
#define TX 32
#define TY 8

__global__ __launch_bounds__(256) void conv_kernel(const float* __restrict__ state)
{
    // union: conv tile (4 ch-groups x 14x38 float4 = 8512 floats) then cat stage (256x36 floats)
    __shared__ __align__(16) float sm_u[9216];
    __shared__ ull sm_cw[392];
    __shared__ ull sm_bias[8];

    int tid = threadIdx.y*TX + threadIdx.x;
    // grid-stride loops — 256 threads must cover all 392+8 words (R2 bug fix)
    for (int i = tid; i < 392; i += 256) sm_cw[i] = g_convp[i];
    if (tid < 8) sm_bias[tid] = g_convbp[tid];

    float4* t4 = (float4*)sm_u;
    int bx0 = blockIdx.x*TX, by0 = blockIdx.y*TY, b = blockIdx.z;

    // load halo tile (38 x 14 pixels x 16 ch), coalesced by (pixel, ch-group)
    for (int i = tid; i < 14*38*4; i += 256){
        int cg = i & 3, pix = i >> 2;
        int py = pix / 38, px = pix - py*38;
        int gy = refl(by0 + py - 3), gx = refl(bx0 + px - 3);
        t4[cg*532 + pix] = *(const float4*)&state[(b*65536 + gy*256 + gx)*CH + cg*4];
    }
    __syncthreads();

    int tx = threadIdx.x, ty = threadIdx.y;
    ull acc[8];
    #pragma unroll
    for (int j = 0; j < 8; j++) acc[j] = sm_bias[j];

    #pragma unroll
    for (int u = 0; u < 7; u++){
        #pragma unroll
        for (int v = 0; v < 7; v++){
            int base = (ty+u)*38 + (tx+v);
            const ull* cw = &sm_cw[(u*7+v)*8];
            #pragma unroll
            for (int cg = 0; cg < 4; cg++){
                float4 val = t4[cg*532 + base];
                acc[2*cg]   = fma2(pack2(val.x, val.y), cw[2*cg],   acc[2*cg]);
                acc[2*cg+1] = fma2(pack2(val.z, val.w), cw[2*cg+1], acc[2*cg+1]);
            }
        }
    }

    float4 s4[4], dv[4];
    #pragma unroll
    for (int cg = 0; cg < 4; cg++){
        s4[cg] = t4[cg*532 + (ty+3)*38 + (tx+3)];
        float4 o;
        unpack2(acc[2*cg],   o.x, o.y);
        unpack2(acc[2*cg+1], o.z, o.w);
        dv[cg] = o;
    }

    int p = b*65536 + (by0+ty)*256 + (bx0+tx);
    float4* dd = (float4*)&g_d[p*CH];
    #pragma unroll
    for (int cg = 0; cg < 4; cg++) dd[cg] = dv[cg];

    __syncthreads();  // done reading tile; reuse smem for cat staging

    float* cs = sm_u;  // cat_s[p_local][36] (stride 36 dodges bank conflicts)
    #pragma unroll
    for (int cg = 0; cg < 4; cg++){
        *(float4*)&cs[tid*36 + cg*4]      = s4[cg];
        *(float4*)&cs[tid*36 + 16 + cg*4] = dv[cg];
    }
    __syncthreads();

    // SYRK: full 32x32 Gram over 256 staged pixels; 64 4x4 tiles x 4 pixel-groups
    int t  = tid & 63, g = tid >> 6;
    int i0 = (t >> 3)*4, j0 = (t & 7)*4;
    ull a2[4][2];
    #pragma unroll
    for (int ia = 0; ia < 4; ia++){ a2[ia][0] = 0ull; a2[ia][1] = 0ull; }

    for (int pp = g; pp < 256; pp += 4){
        float4 av = *(const float4*)&cs[pp*36 + i0];
        float4 bv = *(const float4*)&cs[pp*36 + j0];
        ull blo = pack2(bv.x, bv.y), bhi = pack2(bv.z, bv.w);
        float am[4] = {av.x, av.y, av.z, av.w};
        #pragma unroll
        for (int ia = 0; ia < 4; ia++){
            ull ad = pack2(am[ia], am[ia]);
            a2[ia][0] = fma2(ad, blo, a2[ia][0]);
            a2[ia][1] = fma2(ad, bhi, a2[ia][1]);
        }
    }
    #pragma unroll
    for (int ia = 0; ia < 4; ia++){
        float x0,x1,x2,x3;
        unpack2(a2[ia][0], x0, x1);
        unpack2(a2[ia][1], x2, x3);
        atomicAdd(&g_S[(i0+ia)*CATN + j0+0], x0);
        atomicAdd(&g_S[(i0+ia)*CATN + j0+1], x1);
        atomicAdd(&g_S[(i0+ia)*CATN + j0+2], x2);
        atomicAdd(&g_S[(i0+ia)*CATN + j0+3], x3);
    }

    if (tid < 128){
        int i = tid & 31, g2 = tid >> 5;
        float ssum = 0.f;
        for (int pp = g2; pp < 256; pp += 4) ssum += cs[pp*36 + i];
        atomicAdd(&g_csum[i], ssum);
    }
}

// ---------------- stats: moments -> BN affine folded into packed fc0 weights -----------------
__global__ void stats_kernel(const float* __restrict__ fc0_w)
{
    __shared__ float Ssh[CATN*CATN];
    __shared__ float mu[CATN];
    int o = threadIdx.x;   // 128 threads
    for (int i = o; i < CATN*CATN; i += HID) Ssh[i] = g_S[i];
    if (o < CATN) mu[o] = g_csum[o] * (1.f/(float)NPIX);
    __syncthreads();

    float w[CATN];
    #pragma unroll
    for (int i = 0; i < CATN; i++) w[i] = fc0_w[o*CATN + i];
    float b0 = g_fc0b[o];
    float m = b0;
    #pragma unroll
    for (int i = 0; i < CATN; i++) m += w[i]*mu[i];

    float q = 0.f;
    for (int i = 0; i < CATN; i++){
        float r = 0.f;
        #pragma unroll
        for (int j = 0; j < CATN; j++) r += w[j]*Ssh[i*CATN + j];
        q += w[i]*r;
    }
    q *= (1.f/(float)NPIX);

    float Eh2   = q + 2.f*b0*(m - b0) + b0*b0;
    float var   = Eh2 - m*m;
    float scale = g_gamma[o] * rsqrtf(var + 1e-5f);
    float shift = g_beta[o] + scale*(b0 - m);

    #pragma unroll
    for (int i = 0; i < CATN; i++){
        float sv = scale*w[i];
        g_fc0p[o*CATN + i] = pack2(sv, sv);
    }
    g_fc1p[o*16 + 15] = pack2(shift, shift);

    __syncthreads();
    // zero moments for next step
    for (int i = o; i < CATN*CATN; i += HID) g_S[i] = 0.f;
    if (o < CATN) g_csum[o] = 0.f;
}

// ---------------- pass 2: fused MLP + folded BN + relu + fc1 + mask + update (f32x2) ---------
__global__ __launch_bounds__(128, 4) void update_kernel(const void* __restrict__ masks,
                                                        int step,
                                                        float* __restrict__ state)
{
    __shared__ ull sw[HID*CATN + HID*16];   // 32KB + 16KB = 48KB exactly
    int tid = threadIdx.x;
    for (int i = tid; i < HID*CATN; i += 128) sw[i] = g_fc0p[i];
    ull* sw1 = &sw[HID*CATN];
    for (int i = tid; i < HID*16; i += 128) sw1[i] = g_fc1p[i];
    __syncthreads();

    int p0 = (blockIdx.x*128 + tid)*2;   // two consecutive pixels per thread

    const float4* s0 = (const float4*)&state[p0*CH];
    const float4* s1 = (const float4*)&state[(p0+1)*CH];
    const float4* d0 = (const float4*)&g_d[p0*CH];
    const float4* d1 = (const float4*)&g_d[(p0+1)*CH];

    ull cat2[CATN];
    #pragma unroll
    for (int cg = 0; cg < 4; cg++){
        float4 a = s0[cg], bq = s1[cg];
        cat2[cg*4+0] = pack2(a.x, bq.x);
        cat2[cg*4+1] = pack2(a.y, bq.y);
        cat2[cg*4+2] = pack2(a.z, bq.z);
        cat2[cg*4+3] = pack2(a.w, bq.w);
    }
    #pragma unroll
    for (int cg = 0; cg < 4; cg++){
        float4 a = d0[cg], bq = d1[cg];
        cat2[16+cg*4+0] = pack2(a.x, bq.x);
        cat2[16+cg*4+1] = pack2(a.y, bq.y);
        cat2[16+cg*4+2] = pack2(a.z, bq.z);
        cat2[16+cg*4+3] = pack2(a.w, bq.w);
    }

    ull delta[KOUT];
    #pragma unroll
    for (int k = 0; k < KOUT; k++) delta[k] = 0ull;

    #pragma unroll 1
    for (int o = 0; o < HID; o++){
        const ull* row = &sw[o*CATN];
        const ull* col = &sw1[o*16];
        ull a0 = col[15];   // folded BN shift
        ull a1 = 0ull;
        #pragma unroll
        for (int i = 0; i < CATN; i += 2){
            a0 = fma2(cat2[i],   row[i],   a0);
            a1 = fma2(cat2[i+1], row[i+1], a1);
        }
        ull hsum = add2(a0, a1);
        float lo, hi; unpack2(hsum, lo, hi);
        lo = fmaxf(lo, 0.f); hi = fmaxf(hi, 0.f);
        ull t2 = pack2(lo, hi);
        #pragma unroll
        for (int k = 0; k < KOUT; k++) delta[k] = fma2(t2, col[k], delta[k]);
    }

    // mask (dtype-adaptive)
    float m0, m1;
    int mode = g_mask_mode;
    int mi0 = step*NPIX + p0;
    if (mode == 0){
        const float* mf = (const float*)masks;
        m0 = mf[mi0]; m1 = mf[mi0+1];
    } else if (mode == 1){
        const int* mm = (const int*)masks;
        m0 = (float)mm[mi0]; m1 = (float)mm[mi0+1];
    } else {
        const unsigned char* mb = (const unsigned char*)masks;
        m0 = (float)mb[mi0]; m1 = (float)mb[mi0+1];
    }

    // state already resident in cat2[0..15] — unpack instead of reloading
    float ov0[16], ov1[16];
    #pragma unroll
    for (int i = 0; i < 16; i++) unpack2(cat2[i], ov0[i], ov1[i]);
    #pragma unroll
    for (int k = 0; k < KOUT; k++){
        float dl, dh; unpack2(delta[k], dl, dh);
        ov0[k+1] += dl*m0;
        ov1[k+1] += dh*m1;
    }
    float4* w0p = (float4*)&state[p0*CH];
    float4* w1p = (float4*)&state[(p0+1)*CH];
    #pragma unroll
    for (int cg = 0; cg < 4; cg++){
        w0p[cg] = *(float4*)&ov0[cg*4];
        w1p[cg] = *(float4*)&ov1[cg*4];
    }
}

// ---------------- launch ----------------
extern "C" void kernel_launch(void* const* d_in, const int* in_sizes, int n_in,
                              void* d_out, int out_size)
{
    // Robust binding: all sizes unique except the three 128-element buffers
    // (fc0_b / bn_gamma / bn_beta), which are classified by content on device.
    const float *x = 0, *conv_w = 0, *conv_b = 0, *fc0_w = 0, *fc1_w = 0;
    const void* masks = 0;
    const float* c128[3] = {0, 0, 0};
    int n128 = 0;
    for (int i = 0; i < n_in; i++){
        int s = in_sizes[i];
        const float* pf = (const float*)d_in[i];
        if      (s == NPIX*CH)    x = pf;
        else if (s == NSTEP*NPIX) masks = d_in[i];
        else if (s == 49*CH)      conv_w = pf;
        else if (s == CH)         conv_b = pf;
        else if (s == HID*CATN)   fc0_w = pf;
        else if (s == KOUT*HID)   fc1_w = pf;
        else if (s == HID && n128 < 3) c128[n128++] = pf;
    }
    // positional fallback (dict order) for anything unmatched
    if (!x)      x      = (const float*)d_in[0];
    if (!masks)  masks  = d_in[1];
    if (!conv_w) conv_w = (const float*)d_in[2];
    if (!conv_b) conv_b = (const float*)d_in[3];
    if (!fc0_w)  fc0_w  = (const float*)d_in[4];
    if (!fc1_w)  fc1_w  = (const float*)d_in[6];
    if (n128 < 3){ c128[0] = (const float*)d_in[5];
                   c128[1] = (const float*)d_in[7];
                   c128[2] = (const float*)d_in[8]; }

    float* state = (float*)d_out;   // d_out doubles as the NHWC state buffer

    init_kernel<<<256, 256>>>(x, conv_w, conv_b, fc1_w, (const float*)masks,
                              c128[0], c128[1], c128[2], state);

    dim3 cgrid(WW/TX, HH/TY, BB);
    dim3 cblk(TX, TY);
    for (int s = 0; s < NSTEP; s++){
        conv_kernel<<<cgrid, cblk>>>(state);
        stats_kernel<<<1, 128>>>(fc0_w);
        update_kernel<<<NPIX/256, 128>>>(masks, s, state);
    }
}

// round 8
// speedup vs baseline: 1.6100x; 1.6100x over previous
#include <cuda_runtime.h>
#include <cstdint>

typedef unsigned long long ull;

#define CH    16
#define CATN  32
#define HID   128
#define KOUT  15
#define BB    8
#define HH    256
#define WW    256
#define NSTEP 10
#define NPIX  (BB*HH*WW)   // 524288

// ---------------- scratch (static __device__ — no allocs) ----------------
__device__ float g_d[NPIX*CH];          // conv output, NHWC, 32MB
__device__ float g_S[CATN*CATN];        // Gram matrix sums
__device__ float g_csum[CATN];          // per-channel sums of cat
__device__ ull   g_fc0p[HID*CATN];      // per-step scale-folded fc0 weights, packed (w,w)
__device__ ull   g_fc1p[HID*16];        // fc1 [o][k] packed (w,w); k=15 slot = BN shift
__device__ ull   g_convp[49*8];         // conv weights [tap][ch-pair]
__device__ ull   g_convbp[8];           // conv bias packed pairs
__device__ float g_fc0b[HID];
__device__ float g_gamma[HID];
__device__ float g_beta[HID];
__device__ int   g_mask_mode;           // 0=float32, 1=int32, 2=byte

// ---------------- f32x2 helpers ----------------
__device__ __forceinline__ ull fma2(ull a, ull b, ull c){
    ull d; asm("fma.rn.f32x2 %0,%1,%2,%3;" : "=l"(d) : "l"(a), "l"(b), "l"(c)); return d;
}
__device__ __forceinline__ ull add2(ull a, ull b){
    ull d; asm("add.rn.f32x2 %0,%1,%2;" : "=l"(d) : "l"(a), "l"(b)); return d;
}
__device__ __forceinline__ ull pack2(float lo, float hi){
    ull r; asm("mov.b64 %0,{%1,%2};" : "=l"(r) : "f"(lo), "f"(hi)); return r;
}
__device__ __forceinline__ void unpack2(ull v, float& lo, float& hi){
    asm("mov.b64 {%0,%1},%2;" : "=f"(lo), "=f"(hi) : "l"(v));
}

// reflect padding index (np.pad mode='reflect'), pad=3 < 256 so single reflection
__device__ __forceinline__ int refl(int t){
    if (t < 0)    t = -t;
    if (t >= 256) t = 510 - t;
    return t;
}

// ---------------- init: copy x->state, pack weights, classify 128-buffers, detect mask dtype ----
__global__ void init_kernel(const float* __restrict__ x,
                            const float* __restrict__ conv_w,
                            const float* __restrict__ conv_b,
                            const float* __restrict__ fc1_w,
                            const float* __restrict__ masks_raw,
                            const float* __restrict__ c0,
                            const float* __restrict__ c1,
                            const float* __restrict__ c2,
                            float* __restrict__ out)
{
    int idx = blockIdx.x*blockDim.x + threadIdx.x;
    int stride = gridDim.x*blockDim.x;
    const float4* xin = (const float4*)x;
    float4* xo = (float4*)out;
    for (int i = idx; i < NPIX*CH/4; i += stride) xo[i] = xin[i];

    if (blockIdx.x == 0){
        __shared__ int sel[3];   // indices of (fc0_b, gamma, beta) among {c0,c1,c2}
        if (threadIdx.x == 0){
            const float* cands[3] = {c0, c1, c2};
            int gi = -1, bi = -1;
            for (int c = 0; c < 3; c++){
                int ones = 0, zeros = 0;
                for (int i = 0; i < 128; i++){
                    float v = cands[c][i];
                    if (v == 1.0f) ones++;
                    if (v == 0.0f) zeros++;
                }
                if (ones == 128 && gi < 0) gi = c;
                else if (zeros == 128 && bi < 0) bi = c;
            }
            int fi;
            if (gi >= 0 && bi >= 0 && gi != bi) fi = 3 - gi - bi;
            else { fi = 0; gi = 1; bi = 2; }   // fallback: dict order fc0_b, gamma, beta
            sel[0] = fi; sel[1] = gi; sel[2] = bi;

            // mask dtype detection: Bernoulli(0.5) data makes these unambiguous.
            int mode = 2;
            bool okf = true;
            for (int i = 0; i < 1024; i++){
                float v = masks_raw[i];
                if (v != 0.f && v != 1.f){ okf = false; break; }
            }
            if (okf) mode = 0;
            else {
                const int* mm = (const int*)masks_raw;
                bool oki = true;
                for (int i = 0; i < 1024; i++){
                    int v = mm[i];
                    if (v != 0 && v != 1){ oki = false; break; }
                }
                mode = oki ? 1 : 2;
            }
            g_mask_mode = mode;
        }
        __syncthreads();
        {
            const float* cands[3] = {c0, c1, c2};
            if (threadIdx.x < 128){
                int t = threadIdx.x;
                g_fc0b[t]  = cands[sel[0]][t];
                g_gamma[t] = cands[sel[1]][t];
                g_beta[t]  = cands[sel[2]][t];
            }
        }
        // conv weights: conv_w[c*49 + tap]; pack channel pairs (2j,2j+1) per tap
        for (int i = threadIdx.x; i < 49*8; i += blockDim.x){
            int t = i >> 3, j = i & 7;
            g_convp[i] = pack2(conv_w[(2*j)*49 + t], conv_w[(2*j+1)*49 + t]);
        }
        if (threadIdx.x < 8)
            g_convbp[threadIdx.x] = pack2(conv_b[2*threadIdx.x], conv_b[2*threadIdx.x+1]);
        // fc1: fc1_w[k*HID + o] -> [o][k] packed; slot 15 = per-step shift (stats writes it)
        for (int i = threadIdx.x; i < HID*16; i += blockDim.x){
            int o = i >> 4, k = i & 15;
            float w = (k < KOUT) ? fc1_w[k*HID + o] : 0.f;
            g_fc1p[i] = pack2(w, w);
        }
        for (int i = threadIdx.x; i < CATN*CATN; i += blockDim.x) g_S[i] = 0.f;
        if (threadIdx.x < CATN) g_csum[threadIdx.x] = 0.f;
    }
}

// ---------------- pass 1: depthwise 7x7 reflect conv (f32x2) + cat moment accumulation -------
#define TX 32
#define TY 8

__global__ __launch_bounds__(256, 3) void conv_kernel(const float* __restrict__ state)
{
    // union: conv tile (4 ch-groups x 14x38 float4 = 8512 floats) then cat stage (256x36 floats)
    __shared__ __align__(16) float sm_u[9216];
    __shared__ ull sm_cw[392];
    __shared__ ull sm_bias[8];
    __shared__ float sG[CATN*CATN];   // block-local Gram accumulator
    __shared__ float sC[128];         // block-local csum partials

    int tid = threadIdx.y*TX + threadIdx.x;
    for (int i = tid; i < 392; i += 256) sm_cw[i] = g_convp[i];
    if (tid < 8) sm_bias[tid] = g_convbp[tid];
    for (int i = tid; i < CATN*CATN; i += 256) sG[i] = 0.f;

    float4* t4 = (float4*)sm_u;
    int bx0 = blockIdx.x*TX, by0 = blockIdx.y*TY, b = blockIdx.z;

    // load halo tile (38 x 14 pixels x 16 ch), coalesced by (pixel, ch-group)
    for (int i = tid; i < 14*38*4; i += 256){
        int cg = i & 3, pix = i >> 2;
        int py = pix / 38, px = pix - py*38;
        int gy = refl(by0 + py - 3), gx = refl(bx0 + px - 3);
        t4[cg*532 + pix] = *(const float4*)&state[(b*65536 + gy*256 + gx)*CH + cg*4];
    }
    __syncthreads();

    int tx = threadIdx.x, ty = threadIdx.y;
    ull acc[8];
    #pragma unroll
    for (int j = 0; j < 8; j++) acc[j] = sm_bias[j];

    #pragma unroll
    for (int u = 0; u < 7; u++){
        #pragma unroll
        for (int v = 0; v < 7; v++){
            int base = (ty+u)*38 + (tx+v);
            const ull* cw = &sm_cw[(u*7+v)*8];
            #pragma unroll
            for (int cg = 0; cg < 4; cg++){
                float4 val = t4[cg*532 + base];
                acc[2*cg]   = fma2(pack2(val.x, val.y), cw[2*cg],   acc[2*cg]);
                acc[2*cg+1] = fma2(pack2(val.z, val.w), cw[2*cg+1], acc[2*cg+1]);
            }
        }
    }

    float4 s4[4], dv[4];
    #pragma unroll
    for (int cg = 0; cg < 4; cg++){
        s4[cg] = t4[cg*532 + (ty+3)*38 + (tx+3)];
        float4 o;
        unpack2(acc[2*cg],   o.x, o.y);
        unpack2(acc[2*cg+1], o.z, o.w);
        dv[cg] = o;
    }

    int p = b*65536 + (by0+ty)*256 + (bx0+tx);
    float4* dd = (float4*)&g_d[p*CH];
    #pragma unroll
    for (int cg = 0; cg < 4; cg++) dd[cg] = dv[cg];

    __syncthreads();  // done reading tile; reuse smem for cat staging

    float* cs = sm_u;  // cat_s[p_local][36] (stride 36 dodges bank conflicts)
    #pragma unroll
    for (int cg = 0; cg < 4; cg++){
        *(float4*)&cs[tid*36 + cg*4]      = s4[cg];
        *(float4*)&cs[tid*36 + 16 + cg*4] = dv[cg];
    }
    __syncthreads();

    // SYRK: full 32x32 Gram over 256 staged pixels; 64 4x4 tiles x 4 pixel-groups
    int t  = tid & 63, g = tid >> 6;
    int i0 = (t >> 3)*4, j0 = (t & 7)*4;
    ull a2[4][2];
    #pragma unroll
    for (int ia = 0; ia < 4; ia++){ a2[ia][0] = 0ull; a2[ia][1] = 0ull; }

    for (int pp = g; pp < 256; pp += 4){
        float4 av = *(const float4*)&cs[pp*36 + i0];
        float4 bv = *(const float4*)&cs[pp*36 + j0];
        ull blo = pack2(bv.x, bv.y), bhi = pack2(bv.z, bv.w);
        float am[4] = {av.x, av.y, av.z, av.w};
        #pragma unroll
        for (int ia = 0; ia < 4; ia++){
            ull ad = pack2(am[ia], am[ia]);
            a2[ia][0] = fma2(ad, blo, a2[ia][0]);
            a2[ia][1] = fma2(ad, bhi, a2[ia][1]);
        }
    }
    // stage into block-local Gram (smem atomics), then 4 global REDs/thread below
    #pragma unroll
    for (int ia = 0; ia < 4; ia++){
        float x0,x1,x2,x3;
        unpack2(a2[ia][0], x0, x1);
        unpack2(a2[ia][1], x2, x3);
        atomicAdd(&sG[(i0+ia)*CATN + j0+0], x0);
        atomicAdd(&sG[(i0+ia)*CATN + j0+1], x1);
        atomicAdd(&sG[(i0+ia)*CATN + j0+2], x2);
        atomicAdd(&sG[(i0+ia)*CATN + j0+3], x3);
    }

    if (tid < 128){
        int i = tid & 31, g2 = tid >> 5;
        float ssum = 0.f;
        for (int pp = g2; pp < 256; pp += 4) ssum += cs[pp*36 + i];
        sC[g2*32 + i] = ssum;   // unique slot per thread, no atomic
    }
    __syncthreads();

    // one global RED per Gram entry per block (4 per thread) + 32 csum REDs per block
    for (int i = tid; i < CATN*CATN; i += 256) atomicAdd(&g_S[i], sG[i]);
    if (tid < 32)
        atomicAdd(&g_csum[tid], sC[tid] + sC[tid+32] + sC[tid+64] + sC[tid+96]);
}

// ---------------- stats: moments -> BN affine folded into packed fc0 weights -----------------
__global__ void stats_kernel(const float* __restrict__ fc0_w)
{
    __shared__ float Ssh[CATN*CATN];
    __shared__ float mu[CATN];
    int o = threadIdx.x;   // 128 threads
    for (int i = o; i < CATN*CATN; i += HID) Ssh[i] = g_S[i];
    if (o < CATN) mu[o] = g_csum[o] * (1.f/(float)NPIX);
    __syncthreads();

    float w[CATN];
    #pragma unroll
    for (int i = 0; i < CATN; i++) w[i] = fc0_w[o*CATN + i];
    float b0 = g_fc0b[o];
    float m = b0;
    #pragma unroll
    for (int i = 0; i < CATN; i++) m += w[i]*mu[i];

    float q = 0.f;
    for (int i = 0; i < CATN; i++){
        float r = 0.f;
        #pragma unroll
        for (int j = 0; j < CATN; j++) r += w[j]*Ssh[i*CATN + j];
        q += w[i]*r;
    }
    q *= (1.f/(float)NPIX);

    float Eh2   = q + 2.f*b0*(m - b0) + b0*b0;
    float var   = Eh2 - m*m;
    float scale = g_gamma[o] * rsqrtf(var + 1e-5f);
    float shift = g_beta[o] + scale*(b0 - m);

    #pragma unroll
    for (int i = 0; i < CATN; i++){
        float sv = scale*w[i];
        g_fc0p[o*CATN + i] = pack2(sv, sv);
    }
    g_fc1p[o*16 + 15] = pack2(shift, shift);

    __syncthreads();
    // zero moments for next step
    for (int i = o; i < CATN*CATN; i += HID) g_S[i] = 0.f;
    if (o < CATN) g_csum[o] = 0.f;
}

// ---------------- pass 2: fused MLP + folded BN + relu + fc1 + mask + update (f32x2) ---------
// launch_bounds (128,3): 170-reg budget -> no spills (R6 profile: regs=124 at the (128,4)
// cap of 128 with L1 at 87% => spill traffic). 3 blocks x 48KB smem = 144KB/SM, 12 warps.
__global__ __launch_bounds__(128, 3) void update_kernel(const void* __restrict__ masks,
                                                        int step,
                                                        float* __restrict__ state)
{
    __shared__ ull sw[HID*CATN + HID*16];   // 32KB + 16KB = 48KB exactly
    int tid = threadIdx.x;
    for (int i = tid; i < HID*CATN; i += 128) sw[i] = g_fc0p[i];
    ull* sw1 = &sw[HID*CATN];
    for (int i = tid; i < HID*16; i += 128) sw1[i] = g_fc1p[i];

    int p0 = (blockIdx.x*128 + tid)*2;   // two consecutive pixels per thread

    // hoist mask load (LDG latency overlapped with weight staging + o-loop)
    float m0, m1;
    {
        int mode = g_mask_mode;
        int mi0 = step*NPIX + p0;
        if (mode == 0){
            const float* mf = (const float*)masks;
            m0 = mf[mi0]; m1 = mf[mi0+1];
        } else if (mode == 1){
            const int* mm = (const int*)masks;
            m0 = (float)mm[mi0]; m1 = (float)mm[mi0+1];
        } else {
            const unsigned char* mb = (const unsigned char*)masks;
            m0 = (float)mb[mi0]; m1 = (float)mb[mi0+1];
        }
    }

    const float4* s0 = (const float4*)&state[p0*CH];
    const float4* s1 = (const float4*)&state[(p0+1)*CH];
    const float4* d0 = (const float4*)&g_d[p0*CH];
    const float4* d1 = (const float4*)&g_d[(p0+1)*CH];

    ull cat2[CATN];
    #pragma unroll
    for (int cg = 0; cg < 4; cg++){
        float4 a = s0[cg], bq = s1[cg];
        cat2[cg*4+0] = pack2(a.x, bq.x);
        cat2[cg*4+1] = pack2(a.y, bq.y);
        cat2[cg*4+2] = pack2(a.z, bq.z);
        cat2[cg*4+3] = pack2(a.w, bq.w);
    }
    #pragma unroll
    for (int cg = 0; cg < 4; cg++){
        float4 a = d0[cg], bq = d1[cg];
        cat2[16+cg*4+0] = pack2(a.x, bq.x);
        cat2[16+cg*4+1] = pack2(a.y, bq.y);
        cat2[16+cg*4+2] = pack2(a.z, bq.z);
        cat2[16+cg*4+3] = pack2(a.w, bq.w);
    }

    __syncthreads();

    ull delta[KOUT];
    #pragma unroll
    for (int k = 0; k < KOUT; k++) delta[k] = 0ull;

    #pragma unroll 2
    for (int o = 0; o < HID; o++){
        const ull* row = &sw[o*CATN];
        const ull* col = &sw1[o*16];
        ull a0 = col[15];   // folded BN shift
        ull a1 = 0ull;
        #pragma unroll
        for (int i = 0; i < CATN; i += 2){
            a0 = fma2(cat2[i],   row[i],   a0);
            a1 = fma2(cat2[i+1], row[i+1], a1);
        }
        ull hsum = add2(a0, a1);
        float lo, hi; unpack2(hsum, lo, hi);
        lo = fmaxf(lo, 0.f); hi = fmaxf(hi, 0.f);
        ull t2 = pack2(lo, hi);
        #pragma unroll
        for (int k = 0; k < KOUT; k++) delta[k] = fma2(t2, col[k], delta[k]);
    }

    // state already resident in cat2[0..15] — unpack instead of reloading
    float ov0[16], ov1[16];
    #pragma unroll
    for (int i = 0; i < 16; i++) unpack2(cat2[i], ov0[i], ov1[i]);
    #pragma unroll
    for (int k = 0; k < KOUT; k++){
        float dl, dh; unpack2(delta[k], dl, dh);
        ov0[k+1] += dl*m0;
        ov1[k+1] += dh*m1;
    }
    float4* w0p = (float4*)&state[p0*CH];
    float4* w1p = (float4*)&state[(p0+1)*CH];
    #pragma unroll
    for (int cg = 0; cg < 4; cg++){
        w0p[cg] = *(float4*)&ov0[cg*4];
        w1p[cg] = *(float4*)&ov1[cg*4];
    }
}

// ---------------- launch ----------------
extern "C" void kernel_launch(void* const* d_in, const int* in_sizes, int n_in,
                              void* d_out, int out_size)
{
    // Robust binding: all sizes unique except the three 128-element buffers
    // (fc0_b / bn_gamma / bn_beta), which are classified by content on device.
    const float *x = 0, *conv_w = 0, *conv_b = 0, *fc0_w = 0, *fc1_w = 0;
    const void* masks = 0;
    const float* c128[3] = {0, 0, 0};
    int n128 = 0;
    for (int i = 0; i < n_in; i++){
        int s = in_sizes[i];
        const float* pf = (const float*)d_in[i];
        if      (s == NPIX*CH)    x = pf;
        else if (s == NSTEP*NPIX) masks = d_in[i];
        else if (s == 49*CH)      conv_w = pf;
        else if (s == CH)         conv_b = pf;
        else if (s == HID*CATN)   fc0_w = pf;
        else if (s == KOUT*HID)   fc1_w = pf;
        else if (s == HID && n128 < 3) c128[n128++] = pf;
    }
    // positional fallback (dict order) for anything unmatched
    if (!x)      x      = (const float*)d_in[0];
    if (!masks)  masks  = d_in[1];
    if (!conv_w) conv_w = (const float*)d_in[2];
    if (!conv_b) conv_b = (const float*)d_in[3];
    if (!fc0_w)  fc0_w  = (const float*)d_in[4];
    if (!fc1_w)  fc1_w  = (const float*)d_in[6];
    if (n128 < 3){ c128[0] = (const float*)d_in[5];
                   c128[1] = (const float*)d_in[7];
                   c128[2] = (const float*)d_in[8]; }

    float* state = (float*)d_out;   // d_out doubles as the NHWC state buffer

    init_kernel<<<256, 256>>>(x, conv_w, conv_b, fc1_w, (const float*)masks,
                              c128[0], c128[1], c128[2], state);

    dim3 cgrid(WW/TX, HH/TY, BB);
    dim3 cblk(TX, TY);
    for (int s = 0; s < NSTEP; s++){
        conv_kernel<<<cgrid, cblk>>>(state);
        stats_kernel<<<1, 128>>>(fc0_w);
        update_kernel<<<NPIX/256, 128>>>(masks, s, state);
    }
}

// round 16
// speedup vs baseline: 1.6243x; 1.0089x over previous
#include <cuda_runtime.h>
#include <cstdint>

typedef unsigned long long ull;

#define CH    16
#define CATN  32
#define HID   128
#define KOUT  15
#define BB    8
#define HH    256
#define WW    256
#define NSTEP 10
#define NPIX  (BB*HH*WW)   // 524288

// ---------------- scratch (static __device__ — no allocs) ----------------
__device__ float g_d[NPIX*CH];          // conv output, NHWC, 32MB
__device__ float g_S[CATN*CATN];        // Gram matrix sums
__device__ float g_csum[CATN];          // per-channel sums of cat
__device__ ull   g_fc0p[HID*CATN];      // per-step scale-folded fc0 weights, packed (w,w)
__device__ ull   g_fc1p[HID*16];        // fc1 [o][k] packed (w,w); k=15 slot = BN shift
__device__ ull   g_convp[49*8];         // conv weights [tap][ch-pair]
__device__ ull   g_convbp[8];           // conv bias packed pairs
__device__ float g_fc0b[HID];
__device__ float g_gamma[HID];
__device__ float g_beta[HID];
__device__ int   g_mask_mode;           // 0=float32, 1=int32, 2=byte

// ---------------- f32x2 helpers ----------------
__device__ __forceinline__ ull fma2(ull a, ull b, ull c){
    ull d; asm("fma.rn.f32x2 %0,%1,%2,%3;" : "=l"(d) : "l"(a), "l"(b), "l"(c)); return d;
}
__device__ __forceinline__ ull add2(ull a, ull b){
    ull d; asm("add.rn.f32x2 %0,%1,%2;" : "=l"(d) : "l"(a), "l"(b)); return d;
}
__device__ __forceinline__ ull pack2(float lo, float hi){
    ull r; asm("mov.b64 %0,{%1,%2};" : "=l"(r) : "f"(lo), "f"(hi)); return r;
}
__device__ __forceinline__ void unpack2(ull v, float& lo, float& hi){
    asm("mov.b64 {%0,%1},%2;" : "=f"(lo), "=f"(hi) : "l"(v));
}

// reflect padding index (np.pad mode='reflect'), pad=3 < 256 so single reflection
__device__ __forceinline__ int refl(int t){
    if (t < 0)    t = -t;
    if (t >= 256) t = 510 - t;
    return t;
}

// ---------------- init: copy x->state, pack weights, classify 128-buffers, detect mask dtype ----
__global__ void init_kernel(const float* __restrict__ x,
                            const float* __restrict__ conv_w,
                            const float* __restrict__ conv_b,
                            const float* __restrict__ fc1_w,
                            const float* __restrict__ masks_raw,
                            const float* __restrict__ c0,
                            const float* __restrict__ c1,
                            const float* __restrict__ c2,
                            float* __restrict__ out)
{
    int idx = blockIdx.x*blockDim.x + threadIdx.x;
    int stride = gridDim.x*blockDim.x;
    const float4* xin = (const float4*)x;
    float4* xo = (float4*)out;
    for (int i = idx; i < NPIX*CH/4; i += stride) xo[i] = xin[i];

    if (blockIdx.x == 0){
        __shared__ int sel[3];   // indices of (fc0_b, gamma, beta) among {c0,c1,c2}
        if (threadIdx.x == 0){
            const float* cands[3] = {c0, c1, c2};
            int gi = -1, bi = -1;
            for (int c = 0; c < 3; c++){
                int ones = 0, zeros = 0;
                for (int i = 0; i < 128; i++){
                    float v = cands[c][i];
                    if (v == 1.0f) ones++;
                    if (v == 0.0f) zeros++;
                }
                if (ones == 128 && gi < 0) gi = c;
                else if (zeros == 128 && bi < 0) bi = c;
            }
            int fi;
            if (gi >= 0 && bi >= 0 && gi != bi) fi = 3 - gi - bi;
            else { fi = 0; gi = 1; bi = 2; }   // fallback: dict order fc0_b, gamma, beta
            sel[0] = fi; sel[1] = gi; sel[2] = bi;

            // mask dtype detection: Bernoulli(0.5) data makes these unambiguous.
            int mode = 2;
            bool okf = true;
            for (int i = 0; i < 1024; i++){
                float v = masks_raw[i];
                if (v != 0.f && v != 1.f){ okf = false; break; }
            }
            if (okf) mode = 0;
            else {
                const int* mm = (const int*)masks_raw;
                bool oki = true;
                for (int i = 0; i < 1024; i++){
                    int v = mm[i];
                    if (v != 0 && v != 1){ oki = false; break; }
                }
                mode = oki ? 1 : 2;
            }
            g_mask_mode = mode;
        }
        __syncthreads();
        {
            const float* cands[3] = {c0, c1, c2};
            if (threadIdx.x < 128){
                int t = threadIdx.x;
                g_fc0b[t]  = cands[sel[0]][t];
                g_gamma[t] = cands[sel[1]][t];
                g_beta[t]  = cands[sel[2]][t];
            }
        }
        // conv weights: conv_w[c*49 + tap]; pack channel pairs (2j,2j+1) per tap
        for (int i = threadIdx.x; i < 49*8; i += blockDim.x){
            int t = i >> 3, j = i & 7;
            g_convp[i] = pack2(conv_w[(2*j)*49 + t], conv_w[(2*j+1)*49 + t]);
        }
        if (threadIdx.x < 8)
            g_convbp[threadIdx.x] = pack2(conv_b[2*threadIdx.x], conv_b[2*threadIdx.x+1]);
        // fc1: fc1_w[k*HID + o] -> [o][k] packed; slot 15 = per-step shift (stats writes it)
        for (int i = threadIdx.x; i < HID*16; i += blockDim.x){
            int o = i >> 4, k = i & 15;
            float w = (k < KOUT) ? fc1_w[k*HID + o] : 0.f;
            g_fc1p[i] = pack2(w, w);
        }
        for (int i = threadIdx.x; i < CATN*CATN; i += blockDim.x) g_S[i] = 0.f;
        if (threadIdx.x < CATN) g_csum[threadIdx.x] = 0.f;
    }
}

// ---------------- pass 1: depthwise 7x7 reflect conv (f32x2) + cat moment accumulation -------
#define TX 32
#define TY 8

__global__ __launch_bounds__(256, 3) void conv_kernel(const float* __restrict__ state)
{
    // union: conv tile (4 ch-groups x 14x38 float4 = 8512 floats) then cat stage (256x36 floats)
    __shared__ __align__(16) float sm_u[9216];
    __shared__ ull sm_cw[392];
    __shared__ ull sm_bias[8];
    __shared__ float sG[CATN*CATN];   // block-local Gram accumulator
    __shared__ float sC[128];         // block-local csum partials

    int tid = threadIdx.y*TX + threadIdx.x;
    for (int i = tid; i < 392; i += 256) sm_cw[i] = g_convp[i];
    if (tid < 8) sm_bias[tid] = g_convbp[tid];
    for (int i = tid; i < CATN*CATN; i += 256) sG[i] = 0.f;

    float4* t4 = (float4*)sm_u;
    int bx0 = blockIdx.x*TX, by0 = blockIdx.y*TY, b = blockIdx.z;

    // load halo tile (38 x 14 pixels x 16 ch), coalesced by (pixel, ch-group)
    for (int i = tid; i < 14*38*4; i += 256){
        int cg = i & 3, pix = i >> 2;
        int py = pix / 38, px = pix - py*38;
        int gy = refl(by0 + py - 3), gx = refl(bx0 + px - 3);
        t4[cg*532 + pix] = *(const float4*)&state[(b*65536 + gy*256 + gx)*CH + cg*4];
    }
    __syncthreads();

    int tx = threadIdx.x, ty = threadIdx.y;
    ull acc[8];
    #pragma unroll
    for (int j = 0; j < 8; j++) acc[j] = sm_bias[j];

    #pragma unroll
    for (int u = 0; u < 7; u++){
        #pragma unroll
        for (int v = 0; v < 7; v++){
            int base = (ty+u)*38 + (tx+v);
            const ull* cw = &sm_cw[(u*7+v)*8];
            #pragma unroll
            for (int cg = 0; cg < 4; cg++){
                float4 val = t4[cg*532 + base];
                acc[2*cg]   = fma2(pack2(val.x, val.y), cw[2*cg],   acc[2*cg]);
                acc[2*cg+1] = fma2(pack2(val.z, val.w), cw[2*cg+1], acc[2*cg+1]);
            }
        }
    }

    float4 s4[4], dv[4];
    #pragma unroll
    for (int cg = 0; cg < 4; cg++){
        s4[cg] = t4[cg*532 + (ty+3)*38 + (tx+3)];
        float4 o;
        unpack2(acc[2*cg],   o.x, o.y);
        unpack2(acc[2*cg+1], o.z, o.w);
        dv[cg] = o;
    }

    int p = b*65536 + (by0+ty)*256 + (bx0+tx);
    float4* dd = (float4*)&g_d[p*CH];
    #pragma unroll
    for (int cg = 0; cg < 4; cg++) dd[cg] = dv[cg];

    __syncthreads();  // done reading tile; reuse smem for cat staging

    float* cs = sm_u;  // cat_s[p_local][36] (stride 36 dodges bank conflicts)
    #pragma unroll
    for (int cg = 0; cg < 4; cg++){
        *(float4*)&cs[tid*36 + cg*4]      = s4[cg];
        *(float4*)&cs[tid*36 + 16 + cg*4] = dv[cg];
    }
    __syncthreads();

    // SYRK: full 32x32 Gram over 256 staged pixels; 64 4x4 tiles x 4 pixel-groups
    int t  = tid & 63, g = tid >> 6;
    int i0 = (t >> 3)*4, j0 = (t & 7)*4;
    ull a2[4][2];
    #pragma unroll
    for (int ia = 0; ia < 4; ia++){ a2[ia][0] = 0ull; a2[ia][1] = 0ull; }

    for (int pp = g; pp < 256; pp += 4){
        float4 av = *(const float4*)&cs[pp*36 + i0];
        float4 bv = *(const float4*)&cs[pp*36 + j0];
        ull blo = pack2(bv.x, bv.y), bhi = pack2(bv.z, bv.w);
        float am[4] = {av.x, av.y, av.z, av.w};
        #pragma unroll
        for (int ia = 0; ia < 4; ia++){
            ull ad = pack2(am[ia], am[ia]);
            a2[ia][0] = fma2(ad, blo, a2[ia][0]);
            a2[ia][1] = fma2(ad, bhi, a2[ia][1]);
        }
    }
    // stage into block-local Gram (smem atomics), then 4 global REDs/thread below
    #pragma unroll
    for (int ia = 0; ia < 4; ia++){
        float x0,x1,x2,x3;
        unpack2(a2[ia][0], x0, x1);
        unpack2(a2[ia][1], x2, x3);
        atomicAdd(&sG[(i0+ia)*CATN + j0+0], x0);
        atomicAdd(&sG[(i0+ia)*CATN + j0+1], x1);
        atomicAdd(&sG[(i0+ia)*CATN + j0+2], x2);
        atomicAdd(&sG[(i0+ia)*CATN + j0+3], x3);
    }

    if (tid < 128){
        int i = tid & 31, g2 = tid >> 5;
        float ssum = 0.f;
        for (int pp = g2; pp < 256; pp += 4) ssum += cs[pp*36 + i];
        sC[g2*32 + i] = ssum;   // unique slot per thread, no atomic
    }
    __syncthreads();

    // one global RED per Gram entry per block (4 per thread) + 32 csum REDs per block
    for (int i = tid; i < CATN*CATN; i += 256) atomicAdd(&g_S[i], sG[i]);
    if (tid < 32)
        atomicAdd(&g_csum[tid], sC[tid] + sC[tid+32] + sC[tid+64] + sC[tid+96]);
}

// ---------------- stats: moments -> BN affine folded into packed fc0 weights -----------------
__global__ void stats_kernel(const float* __restrict__ fc0_w)
{
    __shared__ float Ssh[CATN*CATN];
    __shared__ float mu[CATN];
    int o = threadIdx.x;   // 128 threads
    for (int i = o; i < CATN*CATN; i += HID) Ssh[i] = g_S[i];
    if (o < CATN) mu[o] = g_csum[o] * (1.f/(float)NPIX);
    __syncthreads();

    float w[CATN];
    #pragma unroll
    for (int i = 0; i < CATN; i++) w[i] = fc0_w[o*CATN + i];
    float b0 = g_fc0b[o];
    float m = b0;
    #pragma unroll
    for (int i = 0; i < CATN; i++) m += w[i]*mu[i];

    float q = 0.f;
    for (int i = 0; i < CATN; i++){
        float r = 0.f;
        #pragma unroll
        for (int j = 0; j < CATN; j++) r += w[j]*Ssh[i*CATN + j];
        q += w[i]*r;
    }
    q *= (1.f/(float)NPIX);

    float Eh2   = q + 2.f*b0*(m - b0) + b0*b0;
    float var   = Eh2 - m*m;
    float scale = g_gamma[o] * rsqrtf(var + 1e-5f);
    float shift = g_beta[o] + scale*(b0 - m);

    #pragma unroll
    for (int i = 0; i < CATN; i++){
        float sv = scale*w[i];
        g_fc0p[o*CATN + i] = pack2(sv, sv);
    }
    g_fc1p[o*16 + 15] = pack2(shift, shift);

    __syncthreads();
    // zero moments for next step
    for (int i = o; i < CATN*CATN; i += HID) g_S[i] = 0.f;
    if (o < CATN) g_csum[o] = 0.f;
}

// ---------------- pass 2: fused MLP + folded BN + relu + fc1 + mask + update (f32x2) ---------
// R8 profile: L1=87% with NO spills (regs=162) => bound by LDS.64 broadcast wavefronts
// (48/o-iter). Fix: ulonglong2 weight loads => LDS.128, 24 wavefronts/o.
__global__ __launch_bounds__(128, 3) void update_kernel(const void* __restrict__ masks,
                                                        int step,
                                                        float* __restrict__ state)
{
    __shared__ __align__(16) ull sw[HID*CATN + HID*16];   // 32KB + 16KB = 48KB exactly
    int tid = threadIdx.x;
    for (int i = tid; i < HID*CATN; i += 128) sw[i] = g_fc0p[i];
    ull* sw1 = &sw[HID*CATN];
    for (int i = tid; i < HID*16; i += 128) sw1[i] = g_fc1p[i];

    int p0 = (blockIdx.x*128 + tid)*2;   // two consecutive pixels per thread

    // hoist mask load (LDG latency overlapped with weight staging + cat loads)
    float m0, m1;
    {
        int mode = g_mask_mode;
        int mi0 = step*NPIX + p0;
        if (mode == 0){
            const float* mf = (const float*)masks;
            m0 = mf[mi0]; m1 = mf[mi0+1];
        } else if (mode == 1){
            const int* mm = (const int*)masks;
            m0 = (float)mm[mi0]; m1 = (float)mm[mi0+1];
        } else {
            const unsigned char* mb = (const unsigned char*)masks;
            m0 = (float)mb[mi0]; m1 = (float)mb[mi0+1];
        }
    }

    const float4* s0 = (const float4*)&state[p0*CH];
    const float4* s1 = (const float4*)&state[(p0+1)*CH];
    const float4* d0 = (const float4*)&g_d[p0*CH];
    const float4* d1 = (const float4*)&g_d[(p0+1)*CH];

    ull cat2[CATN];
    #pragma unroll
    for (int cg = 0; cg < 4; cg++){
        float4 a = s0[cg], bq = s1[cg];
        cat2[cg*4+0] = pack2(a.x, bq.x);
        cat2[cg*4+1] = pack2(a.y, bq.y);
        cat2[cg*4+2] = pack2(a.z, bq.z);
        cat2[cg*4+3] = pack2(a.w, bq.w);
    }
    #pragma unroll
    for (int cg = 0; cg < 4; cg++){
        float4 a = d0[cg], bq = d1[cg];
        cat2[16+cg*4+0] = pack2(a.x, bq.x);
        cat2[16+cg*4+1] = pack2(a.y, bq.y);
        cat2[16+cg*4+2] = pack2(a.z, bq.z);
        cat2[16+cg*4+3] = pack2(a.w, bq.w);
    }

    __syncthreads();

    ull delta[KOUT];
    #pragma unroll
    for (int k = 0; k < KOUT; k++) delta[k] = 0ull;

    #pragma unroll 2
    for (int o = 0; o < HID; o++){
        const ulonglong2* row = (const ulonglong2*)&sw[o*CATN];   // 256B-aligned
        const ulonglong2* col = (const ulonglong2*)&sw1[o*16];    // 128B-aligned
        ulonglong2 c7 = col[7];          // {fc1[o][14], BN shift}
        ull a0 = c7.y;                   // folded BN shift
        ull a1 = 0ull;
        #pragma unroll
        for (int i = 0; i < 16; i += 2){
            ulonglong2 r0 = row[i];
            ulonglong2 r1 = row[i+1];
            a0 = fma2(cat2[2*i],   r0.x, a0);
            a1 = fma2(cat2[2*i+1], r0.y, a1);
            a0 = fma2(cat2[2*i+2], r1.x, a0);
            a1 = fma2(cat2[2*i+3], r1.y, a1);
        }
        ull hsum = add2(a0, a1);
        float lo, hi; unpack2(hsum, lo, hi);
        lo = fmaxf(lo, 0.f); hi = fmaxf(hi, 0.f);
        ull t2 = pack2(lo, hi);
        #pragma unroll
        for (int k = 0; k < 7; k++){
            ulonglong2 cc = col[k];
            delta[2*k]   = fma2(t2, cc.x, delta[2*k]);
            delta[2*k+1] = fma2(t2, cc.y, delta[2*k+1]);
        }
        delta[14] = fma2(t2, c7.x, delta[14]);
    }

    // state already resident in cat2[0..15] — unpack instead of reloading
    float ov0[16], ov1[16];
    #pragma unroll
    for (int i = 0; i < 16; i++) unpack2(cat2[i], ov0[i], ov1[i]);
    #pragma unroll
    for (int k = 0; k < KOUT; k++){
        float dl, dh; unpack2(delta[k], dl, dh);
        ov0[k+1] += dl*m0;
        ov1[k+1] += dh*m1;
    }
    float4* w0p = (float4*)&state[p0*CH];
    float4* w1p = (float4*)&state[(p0+1)*CH];
    #pragma unroll
    for (int cg = 0; cg < 4; cg++){
        w0p[cg] = *(float4*)&ov0[cg*4];
        w1p[cg] = *(float4*)&ov1[cg*4];
    }
}

// ---------------- launch ----------------
extern "C" void kernel_launch(void* const* d_in, const int* in_sizes, int n_in,
                              void* d_out, int out_size)
{
    // Robust binding: all sizes unique except the three 128-element buffers
    // (fc0_b / bn_gamma / bn_beta), which are classified by content on device.
    const float *x = 0, *conv_w = 0, *conv_b = 0, *fc0_w = 0, *fc1_w = 0;
    const void* masks = 0;
    const float* c128[3] = {0, 0, 0};
    int n128 = 0;
    for (int i = 0; i < n_in; i++){
        int s = in_sizes[i];
        const float* pf = (const float*)d_in[i];
        if      (s == NPIX*CH)    x = pf;
        else if (s == NSTEP*NPIX) masks = d_in[i];
        else if (s == 49*CH)      conv_w = pf;
        else if (s == CH)         conv_b = pf;
        else if (s == HID*CATN)   fc0_w = pf;
        else if (s == KOUT*HID)   fc1_w = pf;
        else if (s == HID && n128 < 3) c128[n128++] = pf;
    }
    // positional fallback (dict order) for anything unmatched
    if (!x)      x      = (const float*)d_in[0];
    if (!masks)  masks  = d_in[1];
    if (!conv_w) conv_w = (const float*)d_in[2];
    if (!conv_b) conv_b = (const float*)d_in[3];
    if (!fc0_w)  fc0_w  = (const float*)d_in[4];
    if (!fc1_w)  fc1_w  = (const float*)d_in[6];
    if (n128 < 3){ c128[0] = (const float*)d_in[5];
                   c128[1] = (const float*)d_in[7];
                   c128[2] = (const float*)d_in[8]; }

    float* state = (float*)d_out;   // d_out doubles as the NHWC state buffer

    init_kernel<<<256, 256>>>(x, conv_w, conv_b, fc1_w, (const float*)masks,
                              c128[0], c128[1], c128[2], state);

    dim3 cgrid(WW/TX, HH/TY, BB);
    dim3 cblk(TX, TY);
    for (int s = 0; s < NSTEP; s++){
        conv_kernel<<<cgrid, cblk>>>(state);
        stats_kernel<<<1, 128>>>(fc0_w);
        update_kernel<<<NPIX/256, 128>>>(masks, s, state);
    }
}